// round 12
// baseline (speedup 1.0000x reference)
#include <cuda_runtime.h>
#include <cuda_bf16.h>
#include <cuda_fp16.h>
#include <cstdint>

typedef __nv_bfloat16 bf16;

#define BZ        16384
#define INPUT_DIM 1024
#define HIDDEN    400
#define EMBED_DIM 256
#define EMBED_NUM 2048

// ===========================================================================
// Scratch (allocation-free __device__ globals)
// Encoder (bf16 3-product): A-ext [m][2*KP] blocks [a0|a1];
//                           B-ext [n][3*KP] blocks [b0|b0|b1]
// Decoder (fp16 1-product): plain fp16 operands.  KP multiples of 64.
// ===========================================================================
__device__ __align__(16) bf16   g_xext [16384L * 2048];  // KP=1024
__device__ __align__(16) bf16   g_h1e  [16384L * 896];   // KP=448
__device__ __align__(16) bf16   g_zee  [16384L * 512];   // KP=256
__device__ __align__(16) bf16   g_w1e  [512L   * 3072];  // N 400->512
__device__ __align__(16) bf16   g_w2e  [256L   * 1344];  // KP=448
__device__ __align__(16) bf16   g_embq [2048L  * 256];   // bf16(emb), VQ prefilter B
__device__ __align__(16) __half g_embh [2048L  * 256];   // fp16(emb), G3 A (gathered)
__device__ __align__(16) __half g_w3h  [512L   * 256];   // N 400->512
__device__ __align__(16) __half g_h3h  [16384L * 448];   // KP=448
__device__ __align__(16) __half g_w4h  [1024L  * 448];   // K 400->448
__device__ __align__(16) __half g_Dh   [16384L * 2048];  // approx VQ distances
__device__ float g_en[EMBED_NUM];
__device__ int   g_idx[BZ];

// ===========================================================================
// PTX helpers
// ===========================================================================
__device__ __forceinline__ uint32_t smem_u32(const void* p) {
    uint32_t a;
    asm("{ .reg .u64 t; cvta.to.shared.u64 t, %1; cvt.u32.u64 %0, t; }"
        : "=r"(a) : "l"(p));
    return a;
}

#define CP_ASYNC16(dst, src) \
    asm volatile("cp.async.cg.shared.global [%0], [%1], 16;" :: "r"(dst), "l"(src) : "memory")
#define CP_COMMIT() asm volatile("cp.async.commit_group;" ::: "memory")
#define CP_WAIT1()  asm volatile("cp.async.wait_group 1;" ::: "memory")
#define CP_WAIT0()  asm volatile("cp.async.wait_group 0;" ::: "memory")

#define LDMX4(r0, r1, r2, r3, addr) \
    asm volatile("ldmatrix.sync.aligned.m8n8.x4.shared.b16 {%0,%1,%2,%3}, [%4];" \
        : "=r"(r0), "=r"(r1), "=r"(r2), "=r"(r3) : "r"(addr))

template <typename T> struct MmaSel;
template <> struct MmaSel<bf16> {
    static __device__ __forceinline__ void run(float* d, const uint32_t* a,
                                               uint32_t b0, uint32_t b1) {
        asm volatile("mma.sync.aligned.m16n8k16.row.col.f32.bf16.bf16.f32 "
            "{%0,%1,%2,%3}, {%4,%5,%6,%7}, {%8,%9}, {%0,%1,%2,%3};"
            : "+f"(d[0]), "+f"(d[1]), "+f"(d[2]), "+f"(d[3])
            : "r"(a[0]), "r"(a[1]), "r"(a[2]), "r"(a[3]), "r"(b0), "r"(b1));
    }
};
template <> struct MmaSel<__half> {
    static __device__ __forceinline__ void run(float* d, const uint32_t* a,
                                               uint32_t b0, uint32_t b1) {
        asm volatile("mma.sync.aligned.m16n8k16.row.col.f32.f16.f16.f32 "
            "{%0,%1,%2,%3}, {%4,%5,%6,%7}, {%8,%9}, {%0,%1,%2,%3};"
            : "+f"(d[0]), "+f"(d[1]), "+f"(d[2]), "+f"(d[3])
            : "r"(a[0]), "r"(a[1]), "r"(a[2]), "r"(a[3]), "r"(b0), "r"(b1));
    }
};

// ===========================================================================
// Prep kernels
// ===========================================================================
__global__ void enorm_kernel(const float* __restrict__ E, float* __restrict__ en) {
    int j    = blockIdx.x * 8 + (threadIdx.x >> 5);
    int lane = threadIdx.x & 31;
    const float* row = E + (long)j * EMBED_DIM;
    float s = 0.f;
    for (int k = lane; k < EMBED_DIM; k += 32) { float v = row[k]; s += v * v; }
    #pragma unroll
    for (int o = 16; o; o >>= 1) s += __shfl_xor_sync(0xFFFFFFFFu, s, o);
    if (lane == 0) en[j] = s;
}

// A-side bf16 2-term split (K == KP)
__global__ void conv_A(const float* __restrict__ in, bf16* __restrict__ out,
                       long rows, int K) {
    long tot = rows * K;
    for (long i = blockIdx.x * 256L + threadIdx.x; i < tot; i += gridDim.x * 256L) {
        long m = i / K;
        int  k = (int)(i - m * K);
        float v = in[i];
        bf16 t0 = __float2bfloat16(v);
        float r = v - __bfloat162float(t0);
        bf16* o = out + m * (2L * K) + k;
        o[0] = t0; o[K] = __float2bfloat16(r);
    }
}

// B-side bf16: blocks [b0|b0|b1]; zero-pads n>=N, k>=K
__global__ void conv_B(const float* __restrict__ W, bf16* __restrict__ out,
                       int N, int Npad, int K, int KP) {
    long tot = (long)Npad * KP;
    for (long i = blockIdx.x * 256L + threadIdx.x; i < tot; i += gridDim.x * 256L) {
        int n = (int)(i / KP);
        int k = (int)(i - (long)n * KP);
        float v = (n < N && k < K) ? W[(long)n * K + k] : 0.f;
        bf16 s0 = __float2bfloat16(v);
        float r = v - __bfloat162float(s0);
        bf16* o = out + (long)n * (3L * KP) + k;
        o[0] = s0; o[KP] = s0; o[2L * KP] = __float2bfloat16(r);
    }
}

// plain fp16 weight conversion with pad
__global__ void conv_Bh(const float* __restrict__ W, __half* __restrict__ out,
                        int N, int Npad, int K, int KP) {
    long tot = (long)Npad * KP;
    for (long i = blockIdx.x * 256L + threadIdx.x; i < tot; i += gridDim.x * 256L) {
        int n = (int)(i / KP);
        int k = (int)(i - (long)n * KP);
        float v = (n < N && k < K) ? W[(long)n * K + k] : 0.f;
        out[i] = __float2half_rn(v);
    }
}

__global__ void f2bf(const float* __restrict__ in, bf16* __restrict__ out, long tot) {
    for (long i = blockIdx.x * 256L + threadIdx.x; i < tot; i += gridDim.x * 256L)
        out[i] = __float2bfloat16(in[i]);
}
__global__ void f2h(const float* __restrict__ in, __half* __restrict__ out, long tot) {
    for (long i = blockIdx.x * 256L + threadIdx.x; i < tot; i += gridDim.x * 256L)
        out[i] = __float2half_rn(in[i]);
}

__global__ void zero_pad(bf16* __restrict__ buf, long rows, int K, int KP) {
    int pad = KP - K;
    long tot = rows * 2L * pad;
    bf16 z = __float2bfloat16(0.f);
    for (long i = blockIdx.x * 256L + threadIdx.x; i < tot; i += gridDim.x * 256L) {
        long m = i / (2 * pad);
        int rem = (int)(i - m * (2 * pad));
        int s = rem / pad, k = K + (rem - (rem / pad) * pad);
        buf[m * (2L * KP) + (long)s * KP + k] = z;
    }
}
__global__ void zero_pad_h(__half* __restrict__ buf, long rows, int K, int KP) {
    int pad = KP - K;
    long tot = rows * pad;
    __half z = __float2half_rn(0.f);
    for (long i = blockIdx.x * 256L + threadIdx.x; i < tot; i += gridDim.x * 256L) {
        long m = i / pad;
        int k = K + (int)(i - m * pad);
        buf[m * (long)KP + k] = z;
    }
}

// ===========================================================================
// VQ scan + exact refine (D in fp16)
// ===========================================================================
#define VQ_DELTA 0.8f

__global__ __launch_bounds__(256)
void scan_refine(const __half* __restrict__ D, const bf16* __restrict__ zee,
                 const float* __restrict__ emb, int* __restrict__ idx) {
    const int wid = threadIdx.x >> 5, lane = threadIdx.x & 31;
    const long row = blockIdx.x * 8 + wid;
    const __half2* d2 = (const __half2*)(D + row * EMBED_NUM);

    float mn = 3.4e38f;
    for (int k = lane; k < EMBED_NUM / 2; k += 32) {
        float2 v = __half22float2(d2[k]);
        mn = fminf(mn, fminf(v.x, v.y));
    }
    #pragma unroll
    for (int o = 16; o; o >>= 1) mn = fminf(mn, __shfl_xor_sync(0xFFFFFFFFu, mn, o));
    const float thr = mn + VQ_DELTA;

    __shared__ int cnt[8];
    __shared__ int cand[8][32];
    if (lane == 0) cnt[wid] = 0;
    __syncwarp();
    for (int k = lane; k < EMBED_NUM / 2; k += 32) {
        float2 v = __half22float2(d2[k]);
        if (v.x <= thr) { int p = atomicAdd(&cnt[wid], 1); if (p < 32) cand[wid][p] = 2 * k; }
        if (v.y <= thr) { int p = atomicAdd(&cnt[wid], 1); if (p < 32) cand[wid][p] = 2 * k + 1; }
    }
    __syncwarp();
    const int nc = min(cnt[wid], 32);

    float z[8];
    #pragma unroll
    for (int t = 0; t < 8; t++) {
        int k = lane + t * 32;
        z[t] = __bfloat162float(zee[row * 512 + k])
             + __bfloat162float(zee[row * 512 + 256 + k]);
    }

    float bd = 3.4e38f; int bi = 0x7FFFFFFF;
    for (int c = 0; c < nc; c++) {
        const int j = cand[wid][c];
        const float* e = emb + (long)j * EMBED_DIM;
        float s = 0.f;
        #pragma unroll
        for (int t = 0; t < 8; t++) {
            float df = z[t] - e[lane + t * 32];
            s = fmaf(df, df, s);
        }
        #pragma unroll
        for (int o = 16; o; o >>= 1) s += __shfl_xor_sync(0xFFFFFFFFu, s, o);
        if (s < bd || (s == bd && j < bi)) { bd = s; bi = j; }
    }
    if (lane == 0) idx[row] = bi;
}

// ===========================================================================
// Persistent HMMA GEMM: BM=128, BN=128, BK=64, NSTG=3 cp.async stages.
// 256 threads, 8 warps = 2(M) x 4(N); warp tile 64x32.
// Persistent CTAs loop over output tiles (kills wave quantization);
// per-warp 16-col N-group masking skips padding MMAs (G1/G3 tails).
// STAGE: 0 = relu + bf16 split store, 1 = bf16 split store,
//        4 = sigmoid fp32 store, 5 = VQ approx D (fp16), 6 = relu fp16 store.
// ===========================================================================
#define NSTG      3
#define STG_STRIDE 36864   // A 128*144 + B 128*144
#define B_STG_OFF  18432
#define PERSIST_GRID 296   // 148 SMs * 2 CTAs

template <int STAGE, bool GATHER, typename T>
__global__ __launch_bounds__(256, 2)
void hgemm(const T* __restrict__ A, int Arow, int KP, int KPC, int NC,
           const T* __restrict__ B, int Brow,
           const float* __restrict__ bias, int Nreal,
           const int* __restrict__ gidx,
           bf16* __restrict__ outE, int outRow, int outKP,
           float* __restrict__ outF,
           __half* __restrict__ outH, int outS,
           int gxTiles, int nTiles) {
    extern __shared__ __align__(16) char smem[];
    const uint32_t smBase = smem_u32(smem);
    const int tid  = threadIdx.x;
    const int lane = tid & 31, wid = tid >> 5;
    const int warpM = wid >> 2, warpN = wid & 3;

    // tile-invariant smem addresses
    const int r4  = tid >> 2;     // 0..63
    const int c16 = tid & 3;
    const uint32_t aD0 = smBase + r4 * 144 + c16 * 16;
    const uint32_t aD1 = aD0 + 64 * 144;
    const uint32_t bD0 = smBase + B_STG_OFF + r4 * 144 + c16 * 16;
    const uint32_t bD1 = bD0 + 64 * 144;
    const int gRow  = lane >> 2;
    const int cPair = (lane & 3) * 2;

    for (int t = blockIdx.x; t < nTiles; t += gridDim.x) {
        const int m0 = (t % gxTiles) * 128;
        const int n0 = (t / gxTiles) * 128;
        const int nwb = n0 + warpN * 32;
        const bool g0ok = (nwb      < Nreal);
        const bool g1ok = (nwb + 16 < Nreal);

        long gr0 = GATHER ? (long)gidx[m0 + r4]      : (long)(m0 + r4);
        long gr1 = GATHER ? (long)gidx[m0 + 64 + r4] : (long)(m0 + 64 + r4);
        const T* aP0 = A + gr0 * (long)Arow;
        const T* aP1 = A + gr1 * (long)Arow;
        const T* bP0 = B + (long)(n0 + r4) * Brow + c16 * 8;
        const T* bP1 = B + (long)(n0 + 64 + r4) * Brow + c16 * 8;

        float acc[4][4][4];
        #pragma unroll
        for (int mt = 0; mt < 4; mt++)
            #pragma unroll
            for (int nt = 0; nt < 4; nt++)
                #pragma unroll
                for (int r = 0; r < 4; r++) acc[mt][nt][r] = 0.f;

        auto issue = [&](int cc) {
            const uint32_t st = (uint32_t)(cc % NSTG) * STG_STRIDE;
            const int p = cc / KPC;
            const int akoff = ((p == 1) ? KP : 0) + (cc - p * KPC) * 64 + c16 * 8;
            const long bk = (long)cc * 64;
            CP_ASYNC16(aD0 + st,      aP0 + akoff);
            CP_ASYNC16(aD0 + st + 64, aP0 + akoff + 32);
            CP_ASYNC16(aD1 + st,      aP1 + akoff);
            CP_ASYNC16(aD1 + st + 64, aP1 + akoff + 32);
            CP_ASYNC16(bD0 + st,      bP0 + bk);
            CP_ASYNC16(bD0 + st + 64, bP0 + bk + 32);
            CP_ASYNC16(bD1 + st,      bP1 + bk);
            CP_ASYNC16(bD1 + st + 64, bP1 + bk + 32);
            CP_COMMIT();
        };

        issue(0);
        if (NC > 1) issue(1);

        for (int c = 0; c < NC; c++) {
            if (c + 1 < NC) CP_WAIT1();
            else            CP_WAIT0();
            __syncthreads();
            if (c + 2 < NC) issue(c + 2);

            const uint32_t st = (uint32_t)(c % NSTG) * STG_STRIDE;
            const uint32_t aW = smBase + st + (warpM * 64) * 144;
            const uint32_t bW = smBase + st + B_STG_OFF + (warpN * 32) * 144;

            #pragma unroll
            for (int kh = 0; kh < 4; kh++) {
                uint32_t a[4][4], bf_[2][4];
                const uint32_t lrow = (lane & 15) * 144;
                const uint32_t lcol = kh * 32 + (lane >> 4) * 16;
                #pragma unroll
                for (int mt = 0; mt < 4; mt++)
                    LDMX4(a[mt][0], a[mt][1], a[mt][2], a[mt][3],
                          aW + (mt * 16) * 144 + lrow + lcol);
                if (g0ok)
                    LDMX4(bf_[0][0], bf_[0][1], bf_[0][2], bf_[0][3],
                          bW + lrow + lcol);
                if (g1ok)
                    LDMX4(bf_[1][0], bf_[1][1], bf_[1][2], bf_[1][3],
                          bW + 16 * 144 + lrow + lcol);
                #pragma unroll
                for (int mt = 0; mt < 4; mt++) {
                    if (g0ok) {
                        MmaSel<T>::run(acc[mt][0], a[mt], bf_[0][0], bf_[0][2]);
                        MmaSel<T>::run(acc[mt][1], a[mt], bf_[0][1], bf_[0][3]);
                    }
                    if (g1ok) {
                        MmaSel<T>::run(acc[mt][2], a[mt], bf_[1][0], bf_[1][2]);
                        MmaSel<T>::run(acc[mt][3], a[mt], bf_[1][1], bf_[1][3]);
                    }
                }
            }
        }
        __syncthreads();

        // ---- epilogue ----
        #pragma unroll
        for (int mt = 0; mt < 4; mt++) {
            #pragma unroll
            for (int nt = 0; nt < 4; nt++) {
                const int n = n0 + warpN * 32 + nt * 8 + cPair;
                if (n >= Nreal) continue;
                const float b0 = bias[n], b1 = bias[n + 1];
                #pragma unroll
                for (int h = 0; h < 2; h++) {
                    const long m = m0 + warpM * 64 + mt * 16 + h * 8 + gRow;
                    if (STAGE == 5) {
                        float v0 = fmaf(-2.f, acc[mt][nt][h * 2 + 0], b0);
                        float v1 = fmaf(-2.f, acc[mt][nt][h * 2 + 1], b1);
                        *(__half2*)(outH + m * (long)outS + n) = __floats2half2_rn(v0, v1);
                        continue;
                    }
                    float v0 = acc[mt][nt][h * 2 + 0] + b0;
                    float v1 = acc[mt][nt][h * 2 + 1] + b1;
                    if (STAGE == 0 || STAGE == 6) { v0 = fmaxf(v0, 0.f); v1 = fmaxf(v1, 0.f); }
                    if (STAGE == 4) {
                        float s0 = 1.f / (1.f + __expf(-v0));
                        float s1 = 1.f / (1.f + __expf(-v1));
                        *(float2*)(outF + m * (long)outS + n) = make_float2(s0, s1);
                    } else if (STAGE == 6) {
                        *(__half2*)(outH + m * (long)outS + n) = __floats2half2_rn(v0, v1);
                    } else {
                        bf16 t00 = __float2bfloat16(v0);
                        bf16 t01 = __float2bfloat16(v1);
                        float r0 = v0 - __bfloat162float(t00);
                        float r1 = v1 - __bfloat162float(t01);
                        bf16* d = outE + m * (long)outRow + n;
                        *(__nv_bfloat162*)(d)         = __nv_bfloat162(t00, t01);
                        *(__nv_bfloat162*)(d + outKP) =
                            __nv_bfloat162(__float2bfloat16(r0), __float2bfloat16(r1));
                    }
                }
            }
        }
        __syncthreads();   // protect smem before next tile's prologue
    }
}

// ===========================================================================
// Launch (order: G1 is the 4th launch -> ncu capture slot)
// ===========================================================================
extern "C" void kernel_launch(void* const* d_in, const int* in_sizes, int n_in,
                              void* d_out, int out_size) {
    const float* x   = (const float*)d_in[0];
    const float* W1  = (const float*)d_in[1];
    const float* b1  = (const float*)d_in[2];
    const float* W2  = (const float*)d_in[3];
    const float* b2  = (const float*)d_in[4];
    const float* W3  = (const float*)d_in[5];
    const float* b3  = (const float*)d_in[6];
    const float* W4  = (const float*)d_in[7];
    const float* b4  = (const float*)d_in[8];
    const float* emb = (const float*)d_in[9];
    float* out = (float*)d_out;

    bf16 *xext, *h1e, *zee, *w1e, *w2e, *embq;
    __half *embh, *w3h, *h3h, *w4h, *Dh;
    float *en; int *idx;
    cudaGetSymbolAddress((void**)&xext, g_xext);
    cudaGetSymbolAddress((void**)&h1e,  g_h1e);
    cudaGetSymbolAddress((void**)&zee,  g_zee);
    cudaGetSymbolAddress((void**)&w1e,  g_w1e);
    cudaGetSymbolAddress((void**)&w2e,  g_w2e);
    cudaGetSymbolAddress((void**)&embq, g_embq);
    cudaGetSymbolAddress((void**)&embh, g_embh);
    cudaGetSymbolAddress((void**)&w3h,  g_w3h);
    cudaGetSymbolAddress((void**)&h3h,  g_h3h);
    cudaGetSymbolAddress((void**)&w4h,  g_w4h);
    cudaGetSymbolAddress((void**)&Dh,   g_Dh);
    cudaGetSymbolAddress((void**)&en,   g_en);
    cudaGetSymbolAddress((void**)&idx,  g_idx);

    const int SMEM = NSTG * STG_STRIDE;  // 110592
    cudaFuncSetAttribute(hgemm<0, false, bf16>,   cudaFuncAttributeMaxDynamicSharedMemorySize, SMEM);
    cudaFuncSetAttribute(hgemm<1, false, bf16>,   cudaFuncAttributeMaxDynamicSharedMemorySize, SMEM);
    cudaFuncSetAttribute(hgemm<5, false, bf16>,   cudaFuncAttributeMaxDynamicSharedMemorySize, SMEM);
    cudaFuncSetAttribute(hgemm<6, true,  __half>, cudaFuncAttributeMaxDynamicSharedMemorySize, SMEM);
    cudaFuncSetAttribute(hgemm<4, false, __half>, cudaFuncAttributeMaxDynamicSharedMemorySize, SMEM);

    // ---- launches 1..3: only G1's dependencies ----
    enorm_kernel<<<EMBED_NUM / 8, 256>>>(emb, en);                     // 1
    conv_A<<<4096, 256>>>(x, xext, (long)BZ, INPUT_DIM);               // 2
    conv_B<<<2048, 256>>>(W1, w1e, HIDDEN, 512, INPUT_DIM, 1024);      // 3

    // ---- launch 4 (ncu slot): G1 = relu(x @ W1^T + b1), persistent ----
    hgemm<0, false, bf16><<<PERSIST_GRID, 256, SMEM>>>(                // 4
        xext, 2048, 1024, 16, 48, w1e, 3072, b1, HIDDEN, nullptr,
        h1e, 896, 448, nullptr, nullptr, 0, 128, 512);

    // ---- remaining prep ----
    conv_B<<<512,  256>>>(W2, w2e, EMBED_DIM, 256, HIDDEN, 448);
    f2bf<<<512, 256>>>(emb, embq, (long)EMBED_NUM * EMBED_DIM);
    f2h <<<512, 256>>>(emb, embh, (long)EMBED_NUM * EMBED_DIM);
    conv_Bh<<<256, 256>>>(W3, w3h, HIDDEN, 512, EMBED_DIM, 256);
    conv_Bh<<<512, 256>>>(W4, w4h, INPUT_DIM, 1024, HIDDEN, 448);
    zero_pad<<<512, 256>>>(h1e, BZ, HIDDEN, 448);
    zero_pad_h<<<512, 256>>>(h3h, BZ, HIDDEN, 448);

    // ---- G2: z_e = h1 @ W2^T + b2, bf16 3-product ----
    hgemm<1, false, bf16><<<256, 256, SMEM>>>(
        h1e, 896, 448, 7, 21, w2e, 1344, b2, EMBED_DIM, nullptr,
        zee, 512, 256, nullptr, nullptr, 0, 128, 256);

    // ---- VQ prefilter: approx D (fp16 store), bf16 1-product ----
    hgemm<5, false, bf16><<<PERSIST_GRID, 256, SMEM>>>(
        zee, 512, 256, 4, 4, embq, 256, en, EMBED_NUM, nullptr,
        nullptr, 0, 0, nullptr, Dh, EMBED_NUM, 128, 2048);

    // ---- VQ exact refine ----
    scan_refine<<<BZ / 8, 256>>>(Dh, zee, emb, idx);

    // ---- G3: h3 = relu(emb[idx] @ W3^T + b3), fp16 1-product, gather ----
    hgemm<6, true, __half><<<PERSIST_GRID, 256, SMEM>>>(
        embh, 256, 256, 4, 4, w3h, 256, b3, HIDDEN, idx,
        nullptr, 0, 0, nullptr, h3h, 448, 128, 512);

    // ---- G4: out = sigmoid(h3 @ W4^T + b4), fp16 1-product ----
    hgemm<4, false, __half><<<PERSIST_GRID, 256, SMEM>>>(
        h3h, 448, 448, 7, 7, w4h, 448, b4, INPUT_DIM, nullptr,
        nullptr, 0, 0, out, nullptr, INPUT_DIM, 128, 1024);
}

// round 14
// speedup vs baseline: 1.4631x; 1.4631x over previous
#include <cuda_runtime.h>
#include <cuda_bf16.h>
#include <cuda_fp16.h>
#include <cstdint>

typedef __nv_bfloat16 bf16;

#define BZ        16384
#define INPUT_DIM 1024
#define HIDDEN    400
#define EMBED_DIM 256
#define EMBED_NUM 2048

// ===========================================================================
// Scratch (allocation-free __device__ globals)
// Encoder (bf16 3-product): A-ext [m][2*KP] blocks [a0|a1];
//                           B-ext [n][3*KP] blocks [b0|b0|b1]
// Decoder (fp16 1-product): plain fp16 operands.  KP multiples of 64.
// ===========================================================================
__device__ __align__(16) bf16   g_xext [16384L * 2048];  // KP=1024
__device__ __align__(16) bf16   g_h1e  [16384L * 896];   // KP=448
__device__ __align__(16) bf16   g_zee  [16384L * 512];   // KP=256
__device__ __align__(16) bf16   g_w1e  [512L   * 3072];  // N 400->512
__device__ __align__(16) bf16   g_w2e  [256L   * 1344];  // KP=448
__device__ __align__(16) bf16   g_embq [2048L  * 256];   // bf16(emb), VQ prefilter B
__device__ __align__(16) __half g_embh [2048L  * 256];   // fp16(emb), G3 A (gathered)
__device__ __align__(16) __half g_w3h  [512L   * 256];   // N 400->512
__device__ __align__(16) __half g_h3h  [16384L * 448];   // KP=448
__device__ __align__(16) __half g_w4h  [1024L  * 448];   // K 400->448
__device__ __align__(16) __half g_Dh   [16384L * 2048];  // approx VQ distances
__device__ float g_en[EMBED_NUM];
__device__ int   g_idx[BZ];

// ===========================================================================
// PTX helpers
// ===========================================================================
__device__ __forceinline__ uint32_t smem_u32(const void* p) {
    uint32_t a;
    asm("{ .reg .u64 t; cvta.to.shared.u64 t, %1; cvt.u32.u64 %0, t; }"
        : "=r"(a) : "l"(p));
    return a;
}

#define CP_ASYNC16(dst, src) \
    asm volatile("cp.async.cg.shared.global [%0], [%1], 16;" :: "r"(dst), "l"(src) : "memory")
#define CP_COMMIT() asm volatile("cp.async.commit_group;" ::: "memory")
#define CP_WAIT1()  asm volatile("cp.async.wait_group 1;" ::: "memory")
#define CP_WAIT0()  asm volatile("cp.async.wait_group 0;" ::: "memory")

#define LDMX4(r0, r1, r2, r3, addr) \
    asm volatile("ldmatrix.sync.aligned.m8n8.x4.shared.b16 {%0,%1,%2,%3}, [%4];" \
        : "=r"(r0), "=r"(r1), "=r"(r2), "=r"(r3) : "r"(addr))

template <typename T> struct MmaSel;
template <> struct MmaSel<bf16> {
    static __device__ __forceinline__ void run(float* d, const uint32_t* a,
                                               uint32_t b0, uint32_t b1) {
        asm volatile("mma.sync.aligned.m16n8k16.row.col.f32.bf16.bf16.f32 "
            "{%0,%1,%2,%3}, {%4,%5,%6,%7}, {%8,%9}, {%0,%1,%2,%3};"
            : "+f"(d[0]), "+f"(d[1]), "+f"(d[2]), "+f"(d[3])
            : "r"(a[0]), "r"(a[1]), "r"(a[2]), "r"(a[3]), "r"(b0), "r"(b1));
    }
};
template <> struct MmaSel<__half> {
    static __device__ __forceinline__ void run(float* d, const uint32_t* a,
                                               uint32_t b0, uint32_t b1) {
        asm volatile("mma.sync.aligned.m16n8k16.row.col.f32.f16.f16.f32 "
            "{%0,%1,%2,%3}, {%4,%5,%6,%7}, {%8,%9}, {%0,%1,%2,%3};"
            : "+f"(d[0]), "+f"(d[1]), "+f"(d[2]), "+f"(d[3])
            : "r"(a[0]), "r"(a[1]), "r"(a[2]), "r"(a[3]), "r"(b0), "r"(b1));
    }
};

// ===========================================================================
// Prep kernels
// ===========================================================================
__global__ void enorm_kernel(const float* __restrict__ E, float* __restrict__ en) {
    int j    = blockIdx.x * 8 + (threadIdx.x >> 5);
    int lane = threadIdx.x & 31;
    const float* row = E + (long)j * EMBED_DIM;
    float s = 0.f;
    for (int k = lane; k < EMBED_DIM; k += 32) { float v = row[k]; s += v * v; }
    #pragma unroll
    for (int o = 16; o; o >>= 1) s += __shfl_xor_sync(0xFFFFFFFFu, s, o);
    if (lane == 0) en[j] = s;
}

// A-side bf16 2-term split (K == KP)
__global__ void conv_A(const float* __restrict__ in, bf16* __restrict__ out,
                       long rows, int K) {
    long tot = rows * K;
    for (long i = blockIdx.x * 256L + threadIdx.x; i < tot; i += gridDim.x * 256L) {
        long m = i / K;
        int  k = (int)(i - m * K);
        float v = in[i];
        bf16 t0 = __float2bfloat16(v);
        float r = v - __bfloat162float(t0);
        bf16* o = out + m * (2L * K) + k;
        o[0] = t0; o[K] = __float2bfloat16(r);
    }
}

// B-side bf16: blocks [b0|b0|b1]; zero-pads n>=N, k>=K
__global__ void conv_B(const float* __restrict__ W, bf16* __restrict__ out,
                       int N, int Npad, int K, int KP) {
    long tot = (long)Npad * KP;
    for (long i = blockIdx.x * 256L + threadIdx.x; i < tot; i += gridDim.x * 256L) {
        int n = (int)(i / KP);
        int k = (int)(i - (long)n * KP);
        float v = (n < N && k < K) ? W[(long)n * K + k] : 0.f;
        bf16 s0 = __float2bfloat16(v);
        float r = v - __bfloat162float(s0);
        bf16* o = out + (long)n * (3L * KP) + k;
        o[0] = s0; o[KP] = s0; o[2L * KP] = __float2bfloat16(r);
    }
}

// plain fp16 weight conversion with pad
__global__ void conv_Bh(const float* __restrict__ W, __half* __restrict__ out,
                        int N, int Npad, int K, int KP) {
    long tot = (long)Npad * KP;
    for (long i = blockIdx.x * 256L + threadIdx.x; i < tot; i += gridDim.x * 256L) {
        int n = (int)(i / KP);
        int k = (int)(i - (long)n * KP);
        float v = (n < N && k < K) ? W[(long)n * K + k] : 0.f;
        out[i] = __float2half_rn(v);
    }
}

__global__ void f2bf(const float* __restrict__ in, bf16* __restrict__ out, long tot) {
    for (long i = blockIdx.x * 256L + threadIdx.x; i < tot; i += gridDim.x * 256L)
        out[i] = __float2bfloat16(in[i]);
}
__global__ void f2h(const float* __restrict__ in, __half* __restrict__ out, long tot) {
    for (long i = blockIdx.x * 256L + threadIdx.x; i < tot; i += gridDim.x * 256L)
        out[i] = __float2half_rn(in[i]);
}

__global__ void zero_pad(bf16* __restrict__ buf, long rows, int K, int KP) {
    int pad = KP - K;
    long tot = rows * 2L * pad;
    bf16 z = __float2bfloat16(0.f);
    for (long i = blockIdx.x * 256L + threadIdx.x; i < tot; i += gridDim.x * 256L) {
        long m = i / (2 * pad);
        int rem = (int)(i - m * (2 * pad));
        int s = rem / pad, k = K + (rem - (rem / pad) * pad);
        buf[m * (2L * KP) + (long)s * KP + k] = z;
    }
}
__global__ void zero_pad_h(__half* __restrict__ buf, long rows, int K, int KP) {
    int pad = KP - K;
    long tot = rows * pad;
    __half z = __float2half_rn(0.f);
    for (long i = blockIdx.x * 256L + threadIdx.x; i < tot; i += gridDim.x * 256L) {
        long m = i / pad;
        int k = K + (int)(i - m * pad);
        buf[m * (long)KP + k] = z;
    }
}

// ===========================================================================
// VQ scan + exact refine (D in fp16)
// ===========================================================================
#define VQ_DELTA 0.8f

__global__ __launch_bounds__(256)
void scan_refine(const __half* __restrict__ D, const bf16* __restrict__ zee,
                 const float* __restrict__ emb, int* __restrict__ idx) {
    const int wid = threadIdx.x >> 5, lane = threadIdx.x & 31;
    const long row = blockIdx.x * 8 + wid;
    const __half2* d2 = (const __half2*)(D + row * EMBED_NUM);

    float mn = 3.4e38f;
    for (int k = lane; k < EMBED_NUM / 2; k += 32) {
        float2 v = __half22float2(d2[k]);
        mn = fminf(mn, fminf(v.x, v.y));
    }
    #pragma unroll
    for (int o = 16; o; o >>= 1) mn = fminf(mn, __shfl_xor_sync(0xFFFFFFFFu, mn, o));
    const float thr = mn + VQ_DELTA;

    __shared__ int cnt[8];
    __shared__ int cand[8][32];
    if (lane == 0) cnt[wid] = 0;
    __syncwarp();
    for (int k = lane; k < EMBED_NUM / 2; k += 32) {
        float2 v = __half22float2(d2[k]);
        if (v.x <= thr) { int p = atomicAdd(&cnt[wid], 1); if (p < 32) cand[wid][p] = 2 * k; }
        if (v.y <= thr) { int p = atomicAdd(&cnt[wid], 1); if (p < 32) cand[wid][p] = 2 * k + 1; }
    }
    __syncwarp();
    const int nc = min(cnt[wid], 32);

    float z[8];
    #pragma unroll
    for (int t = 0; t < 8; t++) {
        int k = lane + t * 32;
        z[t] = __bfloat162float(zee[row * 512 + k])
             + __bfloat162float(zee[row * 512 + 256 + k]);
    }

    float bd = 3.4e38f; int bi = 0x7FFFFFFF;
    for (int c = 0; c < nc; c++) {
        const int j = cand[wid][c];
        const float* e = emb + (long)j * EMBED_DIM;
        float s = 0.f;
        #pragma unroll
        for (int t = 0; t < 8; t++) {
            float df = z[t] - e[lane + t * 32];
            s = fmaf(df, df, s);
        }
        #pragma unroll
        for (int o = 16; o; o >>= 1) s += __shfl_xor_sync(0xFFFFFFFFu, s, o);
        if (s < bd || (s == bd && j < bi)) { bd = s; bi = j; }
    }
    if (lane == 0) idx[row] = bi;
}

// ===========================================================================
// HMMA GEMM: BM=128, BN=128, BK=64 per iteration, NSTG=3 cp.async stages.
// 256 threads, 8 warps = 2(M) x 4(N); warp tile 64x32. Grid-launched (R11
// structure) + warp-uniform N-group masking: warps whose 16-col group lies
// entirely in the zero padding (n >= Nreal) skip LDSM-B and the 32 MMAs.
// STAGE: 0 = relu + bf16 split store, 1 = bf16 split store,
//        4 = sigmoid fp32 store, 5 = VQ approx D (fp16), 6 = relu fp16 store.
// ===========================================================================
#define NSTG      3
#define STG_STRIDE 36864   // A 128*144 + B 128*144
#define B_STG_OFF  18432

template <int STAGE, bool GATHER, typename T>
__global__ __launch_bounds__(256, 2)
void hgemm(const T* __restrict__ A, int Arow, int KP, int KPC, int NC,
           const T* __restrict__ B, int Brow,
           const float* __restrict__ bias, int Nreal,
           const int* __restrict__ gidx,
           bf16* __restrict__ outE, int outRow, int outKP,
           float* __restrict__ outF,
           __half* __restrict__ outH, int outS) {
    extern __shared__ __align__(16) char smem[];
    const uint32_t smBase = smem_u32(smem);
    const int tid  = threadIdx.x;
    const int lane = tid & 31, wid = tid >> 5;
    const int warpM = wid >> 2, warpN = wid & 3;
    const int m0 = blockIdx.x * 128;
    const int n0 = blockIdx.y * 128;

    // warp-uniform N-group masking (padding region is all zeros)
    const int nwb = n0 + warpN * 32;
    const bool g0ok = (nwb      < Nreal);
    const bool g1ok = (nwb + 16 < Nreal);

    // ---- cp.async: thread covers rows {r4, r4+64}, 16B segs {c16, c16+4}
    const int r4  = tid >> 2;     // 0..63
    const int c16 = tid & 3;
    long gr0 = GATHER ? (long)gidx[m0 + r4]      : (long)(m0 + r4);
    long gr1 = GATHER ? (long)gidx[m0 + 64 + r4] : (long)(m0 + 64 + r4);
    const T* aP0 = A + gr0 * (long)Arow;
    const T* aP1 = A + gr1 * (long)Arow;
    const T* bP0 = B + (long)(n0 + r4) * Brow + c16 * 8;
    const T* bP1 = B + (long)(n0 + 64 + r4) * Brow + c16 * 8;
    const uint32_t aD0 = smBase + r4 * 144 + c16 * 16;
    const uint32_t aD1 = aD0 + 64 * 144;
    const uint32_t bD0 = smBase + B_STG_OFF + r4 * 144 + c16 * 16;
    const uint32_t bD1 = bD0 + 64 * 144;

    float acc[4][4][4];
    #pragma unroll
    for (int mt = 0; mt < 4; mt++)
        #pragma unroll
        for (int nt = 0; nt < 4; nt++)
            #pragma unroll
            for (int r = 0; r < 4; r++) acc[mt][nt][r] = 0.f;

    auto issue = [&](int cc) {
        const uint32_t st = (uint32_t)(cc % NSTG) * STG_STRIDE;
        const int p = cc / KPC;
        const int akoff = ((p == 1) ? KP : 0) + (cc - p * KPC) * 64 + c16 * 8;
        const long bk = (long)cc * 64;
        CP_ASYNC16(aD0 + st,      aP0 + akoff);
        CP_ASYNC16(aD0 + st + 64, aP0 + akoff + 32);
        CP_ASYNC16(aD1 + st,      aP1 + akoff);
        CP_ASYNC16(aD1 + st + 64, aP1 + akoff + 32);
        CP_ASYNC16(bD0 + st,      bP0 + bk);
        CP_ASYNC16(bD0 + st + 64, bP0 + bk + 32);
        CP_ASYNC16(bD1 + st,      bP1 + bk);
        CP_ASYNC16(bD1 + st + 64, bP1 + bk + 32);
        CP_COMMIT();
    };

    issue(0);
    if (NC > 1) issue(1);

    const int gRow  = lane >> 2;
    const int cPair = (lane & 3) * 2;

    for (int c = 0; c < NC; c++) {
        if (c + 1 < NC) CP_WAIT1();
        else            CP_WAIT0();
        __syncthreads();
        if (c + 2 < NC) issue(c + 2);

        const uint32_t st = (uint32_t)(c % NSTG) * STG_STRIDE;
        const uint32_t aW = smBase + st + (warpM * 64) * 144;
        const uint32_t bW = smBase + st + B_STG_OFF + (warpN * 32) * 144;

        #pragma unroll
        for (int kh = 0; kh < 4; kh++) {
            uint32_t a[4][4], bf_[2][4];
            const uint32_t lrow = (lane & 15) * 144;
            const uint32_t lcol = kh * 32 + (lane >> 4) * 16;
            #pragma unroll
            for (int mt = 0; mt < 4; mt++)
                LDMX4(a[mt][0], a[mt][1], a[mt][2], a[mt][3],
                      aW + (mt * 16) * 144 + lrow + lcol);
            if (g0ok)
                LDMX4(bf_[0][0], bf_[0][1], bf_[0][2], bf_[0][3],
                      bW + lrow + lcol);
            if (g1ok)
                LDMX4(bf_[1][0], bf_[1][1], bf_[1][2], bf_[1][3],
                      bW + 16 * 144 + lrow + lcol);
            #pragma unroll
            for (int mt = 0; mt < 4; mt++) {
                if (g0ok) {
                    MmaSel<T>::run(acc[mt][0], a[mt], bf_[0][0], bf_[0][2]);
                    MmaSel<T>::run(acc[mt][1], a[mt], bf_[0][1], bf_[0][3]);
                }
                if (g1ok) {
                    MmaSel<T>::run(acc[mt][2], a[mt], bf_[1][0], bf_[1][2]);
                    MmaSel<T>::run(acc[mt][3], a[mt], bf_[1][1], bf_[1][3]);
                }
            }
        }
    }
    __syncthreads();

    // ---- epilogue ----
    #pragma unroll
    for (int mt = 0; mt < 4; mt++) {
        #pragma unroll
        for (int nt = 0; nt < 4; nt++) {
            const int n = n0 + warpN * 32 + nt * 8 + cPair;
            if (n >= Nreal) continue;
            const float b0 = bias[n], b1 = bias[n + 1];
            #pragma unroll
            for (int h = 0; h < 2; h++) {
                const long m = m0 + warpM * 64 + mt * 16 + h * 8 + gRow;
                if (STAGE == 5) {
                    float v0 = fmaf(-2.f, acc[mt][nt][h * 2 + 0], b0);
                    float v1 = fmaf(-2.f, acc[mt][nt][h * 2 + 1], b1);
                    *(__half2*)(outH + m * (long)outS + n) = __floats2half2_rn(v0, v1);
                    continue;
                }
                float v0 = acc[mt][nt][h * 2 + 0] + b0;
                float v1 = acc[mt][nt][h * 2 + 1] + b1;
                if (STAGE == 0 || STAGE == 6) { v0 = fmaxf(v0, 0.f); v1 = fmaxf(v1, 0.f); }
                if (STAGE == 4) {
                    float s0 = 1.f / (1.f + __expf(-v0));
                    float s1 = 1.f / (1.f + __expf(-v1));
                    *(float2*)(outF + m * (long)outS + n) = make_float2(s0, s1);
                } else if (STAGE == 6) {
                    *(__half2*)(outH + m * (long)outS + n) = __floats2half2_rn(v0, v1);
                } else {
                    bf16 t00 = __float2bfloat16(v0);
                    bf16 t01 = __float2bfloat16(v1);
                    float r0 = v0 - __bfloat162float(t00);
                    float r1 = v1 - __bfloat162float(t01);
                    bf16* d = outE + m * (long)outRow + n;
                    *(__nv_bfloat162*)(d)         = __nv_bfloat162(t00, t01);
                    *(__nv_bfloat162*)(d + outKP) =
                        __nv_bfloat162(__float2bfloat16(r0), __float2bfloat16(r1));
                }
            }
        }
    }
}

// ===========================================================================
// Launch (order: G1 is the 4th launch -> ncu capture slot)
// ===========================================================================
extern "C" void kernel_launch(void* const* d_in, const int* in_sizes, int n_in,
                              void* d_out, int out_size) {
    const float* x   = (const float*)d_in[0];
    const float* W1  = (const float*)d_in[1];
    const float* b1  = (const float*)d_in[2];
    const float* W2  = (const float*)d_in[3];
    const float* b2  = (const float*)d_in[4];
    const float* W3  = (const float*)d_in[5];
    const float* b3  = (const float*)d_in[6];
    const float* W4  = (const float*)d_in[7];
    const float* b4  = (const float*)d_in[8];
    const float* emb = (const float*)d_in[9];
    float* out = (float*)d_out;

    bf16 *xext, *h1e, *zee, *w1e, *w2e, *embq;
    __half *embh, *w3h, *h3h, *w4h, *Dh;
    float *en; int *idx;
    cudaGetSymbolAddress((void**)&xext, g_xext);
    cudaGetSymbolAddress((void**)&h1e,  g_h1e);
    cudaGetSymbolAddress((void**)&zee,  g_zee);
    cudaGetSymbolAddress((void**)&w1e,  g_w1e);
    cudaGetSymbolAddress((void**)&w2e,  g_w2e);
    cudaGetSymbolAddress((void**)&embq, g_embq);
    cudaGetSymbolAddress((void**)&embh, g_embh);
    cudaGetSymbolAddress((void**)&w3h,  g_w3h);
    cudaGetSymbolAddress((void**)&h3h,  g_h3h);
    cudaGetSymbolAddress((void**)&w4h,  g_w4h);
    cudaGetSymbolAddress((void**)&Dh,   g_Dh);
    cudaGetSymbolAddress((void**)&en,   g_en);
    cudaGetSymbolAddress((void**)&idx,  g_idx);

    const int SMEM = NSTG * STG_STRIDE;  // 110592
    cudaFuncSetAttribute(hgemm<0, false, bf16>,   cudaFuncAttributeMaxDynamicSharedMemorySize, SMEM);
    cudaFuncSetAttribute(hgemm<1, false, bf16>,   cudaFuncAttributeMaxDynamicSharedMemorySize, SMEM);
    cudaFuncSetAttribute(hgemm<5, false, bf16>,   cudaFuncAttributeMaxDynamicSharedMemorySize, SMEM);
    cudaFuncSetAttribute(hgemm<6, true,  __half>, cudaFuncAttributeMaxDynamicSharedMemorySize, SMEM);
    cudaFuncSetAttribute(hgemm<4, false, __half>, cudaFuncAttributeMaxDynamicSharedMemorySize, SMEM);

    // ---- launches 1..3: only G1's dependencies ----
    enorm_kernel<<<EMBED_NUM / 8, 256>>>(emb, en);                     // 1
    conv_A<<<4096, 256>>>(x, xext, (long)BZ, INPUT_DIM);               // 2
    conv_B<<<2048, 256>>>(W1, w1e, HIDDEN, 512, INPUT_DIM, 1024);      // 3

    // ---- launch 4 (ncu slot): G1 = relu(x @ W1^T + b1) ----
    hgemm<0, false, bf16><<<dim3(128, 4), 256, SMEM>>>(                // 4
        xext, 2048, 1024, 16, 48, w1e, 3072, b1, HIDDEN, nullptr,
        h1e, 896, 448, nullptr, nullptr, 0);

    // ---- remaining prep ----
    conv_B<<<512,  256>>>(W2, w2e, EMBED_DIM, 256, HIDDEN, 448);
    f2bf<<<512, 256>>>(emb, embq, (long)EMBED_NUM * EMBED_DIM);
    f2h <<<512, 256>>>(emb, embh, (long)EMBED_NUM * EMBED_DIM);
    conv_Bh<<<256, 256>>>(W3, w3h, HIDDEN, 512, EMBED_DIM, 256);
    conv_Bh<<<512, 256>>>(W4, w4h, INPUT_DIM, 1024, HIDDEN, 448);
    zero_pad<<<512, 256>>>(h1e, BZ, HIDDEN, 448);
    zero_pad_h<<<512, 256>>>(h3h, BZ, HIDDEN, 448);

    // ---- G2: z_e = h1 @ W2^T + b2, bf16 3-product ----
    hgemm<1, false, bf16><<<dim3(128, 2), 256, SMEM>>>(
        h1e, 896, 448, 7, 21, w2e, 1344, b2, EMBED_DIM, nullptr,
        zee, 512, 256, nullptr, nullptr, 0);

    // ---- VQ prefilter: approx D (fp16 store), bf16 1-product ----
    hgemm<5, false, bf16><<<dim3(128, 16), 256, SMEM>>>(
        zee, 512, 256, 4, 4, embq, 256, en, EMBED_NUM, nullptr,
        nullptr, 0, 0, nullptr, Dh, EMBED_NUM);

    // ---- VQ exact refine ----
    scan_refine<<<BZ / 8, 256>>>(Dh, zee, emb, idx);

    // ---- G3: h3 = relu(emb[idx] @ W3^T + b3), fp16 1-product, gather ----
    hgemm<6, true, __half><<<dim3(128, 4), 256, SMEM>>>(
        embh, 256, 256, 4, 4, w3h, 256, b3, HIDDEN, idx,
        nullptr, 0, 0, nullptr, h3h, 448);

    // ---- G4: out = sigmoid(h3 @ W4^T + b4), fp16 1-product ----
    hgemm<4, false, __half><<<dim3(128, 8), 256, SMEM>>>(
        h3h, 448, 448, 7, 7, w4h, 448, b4, INPUT_DIM, nullptr,
        nullptr, 0, 0, out, nullptr, INPUT_DIM);
}

// round 16
// speedup vs baseline: 1.5589x; 1.0654x over previous
#include <cuda_runtime.h>
#include <cuda_bf16.h>
#include <cuda_fp16.h>
#include <cstdint>

typedef __nv_bfloat16 bf16;

#define BZ        16384
#define INPUT_DIM 1024
#define HIDDEN    400
#define EMBED_DIM 256
#define EMBED_NUM 2048

// ===========================================================================
// Scratch (allocation-free __device__ globals)
// Encoder (bf16 3-product): A-ext [m][2*KP] blocks [a0|a1];
//                           B-ext [n][3*KP] blocks [b0|b0|b1]
// Decoder (fp16 1-product): plain fp16 operands.  KP multiples of 64.
// ===========================================================================
__device__ __align__(16) bf16   g_xext [16384L * 2048];  // KP=1024
__device__ __align__(16) bf16   g_h1e  [16384L * 896];   // KP=448
__device__ __align__(16) bf16   g_zee  [16384L * 512];   // KP=256
__device__ __align__(16) bf16   g_w1e  [512L   * 3072];  // N 400->512
__device__ __align__(16) bf16   g_w2e  [256L   * 1344];  // KP=448
__device__ __align__(16) bf16   g_embq [2048L  * 256];   // bf16(emb), VQ prefilter B
__device__ __align__(16) __half g_embh [2048L  * 256];   // fp16(emb), G3 A (gathered)
__device__ __align__(16) __half g_w3h  [512L   * 256];   // N 400->512
__device__ __align__(16) __half g_h3h  [16384L * 448];   // KP=448
__device__ __align__(16) __half g_w4h  [1024L  * 448];   // K 400->448
__device__ __align__(16) __half g_Dh   [16384L * 2048];  // approx VQ distances
__device__ float g_en[EMBED_NUM];
__device__ int   g_idx[BZ];

// ===========================================================================
// PTX helpers
// ===========================================================================
__device__ __forceinline__ uint32_t smem_u32(const void* p) {
    uint32_t a;
    asm("{ .reg .u64 t; cvta.to.shared.u64 t, %1; cvt.u32.u64 %0, t; }"
        : "=r"(a) : "l"(p));
    return a;
}

#define CP_ASYNC16(dst, src) \
    asm volatile("cp.async.cg.shared.global [%0], [%1], 16;" :: "r"(dst), "l"(src) : "memory")
#define CP_COMMIT() asm volatile("cp.async.commit_group;" ::: "memory")
#define CP_WAIT1()  asm volatile("cp.async.wait_group 1;" ::: "memory")
#define CP_WAIT0()  asm volatile("cp.async.wait_group 0;" ::: "memory")

#define LDMX4(r0, r1, r2, r3, addr) \
    asm volatile("ldmatrix.sync.aligned.m8n8.x4.shared.b16 {%0,%1,%2,%3}, [%4];" \
        : "=r"(r0), "=r"(r1), "=r"(r2), "=r"(r3) : "r"(addr))

template <typename T> struct MmaSel;
template <> struct MmaSel<bf16> {
    static __device__ __forceinline__ void run(float* d, const uint32_t* a,
                                               uint32_t b0, uint32_t b1) {
        asm volatile("mma.sync.aligned.m16n8k16.row.col.f32.bf16.bf16.f32 "
            "{%0,%1,%2,%3}, {%4,%5,%6,%7}, {%8,%9}, {%0,%1,%2,%3};"
            : "+f"(d[0]), "+f"(d[1]), "+f"(d[2]), "+f"(d[3])
            : "r"(a[0]), "r"(a[1]), "r"(a[2]), "r"(a[3]), "r"(b0), "r"(b1));
    }
};
template <> struct MmaSel<__half> {
    static __device__ __forceinline__ void run(float* d, const uint32_t* a,
                                               uint32_t b0, uint32_t b1) {
        asm volatile("mma.sync.aligned.m16n8k16.row.col.f32.f16.f16.f32 "
            "{%0,%1,%2,%3}, {%4,%5,%6,%7}, {%8,%9}, {%0,%1,%2,%3};"
            : "+f"(d[0]), "+f"(d[1]), "+f"(d[2]), "+f"(d[3])
            : "r"(a[0]), "r"(a[1]), "r"(a[2]), "r"(a[3]), "r"(b0), "r"(b1));
    }
};

// ===========================================================================
// Prep kernels
// ===========================================================================
__global__ void enorm_kernel(const float* __restrict__ E, float* __restrict__ en) {
    int j    = blockIdx.x * 8 + (threadIdx.x >> 5);
    int lane = threadIdx.x & 31;
    const float* row = E + (long)j * EMBED_DIM;
    float s = 0.f;
    for (int k = lane; k < EMBED_DIM; k += 32) { float v = row[k]; s += v * v; }
    #pragma unroll
    for (int o = 16; o; o >>= 1) s += __shfl_xor_sync(0xFFFFFFFFu, s, o);
    if (lane == 0) en[j] = s;
}

// A-side bf16 2-term split, vectorized 4-wide (K multiple of 4, K == KP)
__global__ void conv_A4(const float4* __restrict__ in, bf16* __restrict__ out,
                        long rows, int K) {
    const int K4 = K >> 2;
    long tot = rows * K4;
    for (long i = blockIdx.x * 256L + threadIdx.x; i < tot; i += gridDim.x * 256L) {
        long m = i / K4;
        int  k4 = (int)(i - m * K4);
        float4 v = in[i];
        bf16 t0 = __float2bfloat16(v.x), t1 = __float2bfloat16(v.y);
        bf16 t2 = __float2bfloat16(v.z), t3 = __float2bfloat16(v.w);
        bf16 r0 = __float2bfloat16(v.x - __bfloat162float(t0));
        bf16 r1 = __float2bfloat16(v.y - __bfloat162float(t1));
        bf16 r2 = __float2bfloat16(v.z - __bfloat162float(t2));
        bf16 r3 = __float2bfloat16(v.w - __bfloat162float(t3));
        bf16* o = out + m * (2L * K) + k4 * 4;
        *(__nv_bfloat162*)(o)         = __nv_bfloat162(t0, t1);
        *(__nv_bfloat162*)(o + 2)     = __nv_bfloat162(t2, t3);
        *(__nv_bfloat162*)(o + K)     = __nv_bfloat162(r0, r1);
        *(__nv_bfloat162*)(o + K + 2) = __nv_bfloat162(r2, r3);
    }
}

// B-side bf16: blocks [b0|b0|b1]; zero-pads n>=N, k>=K
__global__ void conv_B(const float* __restrict__ W, bf16* __restrict__ out,
                       int N, int Npad, int K, int KP) {
    long tot = (long)Npad * KP;
    for (long i = blockIdx.x * 256L + threadIdx.x; i < tot; i += gridDim.x * 256L) {
        int n = (int)(i / KP);
        int k = (int)(i - (long)n * KP);
        float v = (n < N && k < K) ? W[(long)n * K + k] : 0.f;
        bf16 s0 = __float2bfloat16(v);
        float r = v - __bfloat162float(s0);
        bf16* o = out + (long)n * (3L * KP) + k;
        o[0] = s0; o[KP] = s0; o[2L * KP] = __float2bfloat16(r);
    }
}

// plain fp16 weight conversion with pad
__global__ void conv_Bh(const float* __restrict__ W, __half* __restrict__ out,
                        int N, int Npad, int K, int KP) {
    long tot = (long)Npad * KP;
    for (long i = blockIdx.x * 256L + threadIdx.x; i < tot; i += gridDim.x * 256L) {
        int n = (int)(i / KP);
        int k = (int)(i - (long)n * KP);
        float v = (n < N && k < K) ? W[(long)n * K + k] : 0.f;
        out[i] = __float2half_rn(v);
    }
}

__global__ void f2bf(const float* __restrict__ in, bf16* __restrict__ out, long tot) {
    for (long i = blockIdx.x * 256L + threadIdx.x; i < tot; i += gridDim.x * 256L)
        out[i] = __float2bfloat16(in[i]);
}
__global__ void f2h(const float* __restrict__ in, __half* __restrict__ out, long tot) {
    for (long i = blockIdx.x * 256L + threadIdx.x; i < tot; i += gridDim.x * 256L)
        out[i] = __float2half_rn(in[i]);
}

__global__ void zero_pad(bf16* __restrict__ buf, long rows, int K, int KP) {
    int pad = KP - K;
    long tot = rows * 2L * pad;
    bf16 z = __float2bfloat16(0.f);
    for (long i = blockIdx.x * 256L + threadIdx.x; i < tot; i += gridDim.x * 256L) {
        long m = i / (2 * pad);
        int rem = (int)(i - m * (2 * pad));
        int s = rem / pad, k = K + (rem - (rem / pad) * pad);
        buf[m * (2L * KP) + (long)s * KP + k] = z;
    }
}
__global__ void zero_pad_h(__half* __restrict__ buf, long rows, int K, int KP) {
    int pad = KP - K;
    long tot = rows * pad;
    __half z = __float2half_rn(0.f);
    for (long i = blockIdx.x * 256L + threadIdx.x; i < tot; i += gridDim.x * 256L) {
        long m = i / pad;
        int k = K + (int)(i - m * pad);
        buf[m * (long)KP + k] = z;
    }
}

// ===========================================================================
// VQ scan + exact refine (D in fp16)
// ===========================================================================
#define VQ_DELTA 0.8f

__global__ __launch_bounds__(256)
void scan_refine(const __half* __restrict__ D, const bf16* __restrict__ zee,
                 const float* __restrict__ emb, int* __restrict__ idx) {
    const int wid = threadIdx.x >> 5, lane = threadIdx.x & 31;
    const long row = blockIdx.x * 8 + wid;
    const __half2* d2 = (const __half2*)(D + row * EMBED_NUM);

    float mn = 3.4e38f;
    for (int k = lane; k < EMBED_NUM / 2; k += 32) {
        float2 v = __half22float2(d2[k]);
        mn = fminf(mn, fminf(v.x, v.y));
    }
    #pragma unroll
    for (int o = 16; o; o >>= 1) mn = fminf(mn, __shfl_xor_sync(0xFFFFFFFFu, mn, o));
    const float thr = mn + VQ_DELTA;

    __shared__ int cnt[8];
    __shared__ int cand[8][32];
    if (lane == 0) cnt[wid] = 0;
    __syncwarp();
    for (int k = lane; k < EMBED_NUM / 2; k += 32) {
        float2 v = __half22float2(d2[k]);
        if (v.x <= thr) { int p = atomicAdd(&cnt[wid], 1); if (p < 32) cand[wid][p] = 2 * k; }
        if (v.y <= thr) { int p = atomicAdd(&cnt[wid], 1); if (p < 32) cand[wid][p] = 2 * k + 1; }
    }
    __syncwarp();
    const int nc = min(cnt[wid], 32);

    float z[8];
    #pragma unroll
    for (int t = 0; t < 8; t++) {
        int k = lane + t * 32;
        z[t] = __bfloat162float(zee[row * 512 + k])
             + __bfloat162float(zee[row * 512 + 256 + k]);
    }

    float bd = 3.4e38f; int bi = 0x7FFFFFFF;
    for (int c = 0; c < nc; c++) {
        const int j = cand[wid][c];
        const float* e = emb + (long)j * EMBED_DIM;
        float s = 0.f;
        #pragma unroll
        for (int t = 0; t < 8; t++) {
            float df = z[t] - e[lane + t * 32];
            s = fmaf(df, df, s);
        }
        #pragma unroll
        for (int o = 16; o; o >>= 1) s += __shfl_xor_sync(0xFFFFFFFFu, s, o);
        if (s < bd || (s == bd && j < bi)) { bd = s; bi = j; }
    }
    if (lane == 0) idx[row] = bi;
}

// ===========================================================================
// HMMA GEMM: BM=128, BN=128, BK=64 per iteration, NSTG=3 cp.async stages.
// 256 threads, 8 warps = 2(M) x 4(N); warp tile 64x32. Grid-launched.
// kh body interleaves LDSM-A with MMA (A[mt+1] prefetched before mt's MMAs)
// to overlap shared-pipe and tensor-pipe phases. MMA order per accumulator
// is unchanged -> bit-identical results.
// STAGE: 0 = relu + bf16 split store, 1 = bf16 split store,
//        4 = sigmoid fp32 store, 5 = VQ approx D (fp16), 6 = relu fp16 store.
// ===========================================================================
#define NSTG      3
#define STG_STRIDE 36864   // A 128*144 + B 128*144
#define B_STG_OFF  18432

template <int STAGE, bool GATHER, typename T>
__global__ __launch_bounds__(256, 2)
void hgemm(const T* __restrict__ A, int Arow, int KP, int KPC, int NC,
           const T* __restrict__ B, int Brow,
           const float* __restrict__ bias, int Nreal,
           const int* __restrict__ gidx,
           bf16* __restrict__ outE, int outRow, int outKP,
           float* __restrict__ outF,
           __half* __restrict__ outH, int outS) {
    extern __shared__ __align__(16) char smem[];
    const uint32_t smBase = smem_u32(smem);
    const int tid  = threadIdx.x;
    const int lane = tid & 31, wid = tid >> 5;
    const int warpM = wid >> 2, warpN = wid & 3;
    const int m0 = blockIdx.x * 128;
    const int n0 = blockIdx.y * 128;

    // ---- cp.async: thread covers rows {r4, r4+64}, 16B segs {c16, c16+4}
    const int r4  = tid >> 2;     // 0..63
    const int c16 = tid & 3;
    long gr0 = GATHER ? (long)gidx[m0 + r4]      : (long)(m0 + r4);
    long gr1 = GATHER ? (long)gidx[m0 + 64 + r4] : (long)(m0 + 64 + r4);
    const T* aP0 = A + gr0 * (long)Arow;
    const T* aP1 = A + gr1 * (long)Arow;
    const T* bP0 = B + (long)(n0 + r4) * Brow + c16 * 8;
    const T* bP1 = B + (long)(n0 + 64 + r4) * Brow + c16 * 8;
    const uint32_t aD0 = smBase + r4 * 144 + c16 * 16;
    const uint32_t aD1 = aD0 + 64 * 144;
    const uint32_t bD0 = smBase + B_STG_OFF + r4 * 144 + c16 * 16;
    const uint32_t bD1 = bD0 + 64 * 144;

    float acc[4][4][4];
    #pragma unroll
    for (int mt = 0; mt < 4; mt++)
        #pragma unroll
        for (int nt = 0; nt < 4; nt++)
            #pragma unroll
            for (int r = 0; r < 4; r++) acc[mt][nt][r] = 0.f;

    auto issue = [&](int cc) {
        const uint32_t st = (uint32_t)(cc % NSTG) * STG_STRIDE;
        const int p = cc / KPC;
        const int akoff = ((p == 1) ? KP : 0) + (cc - p * KPC) * 64 + c16 * 8;
        const long bk = (long)cc * 64;
        CP_ASYNC16(aD0 + st,      aP0 + akoff);
        CP_ASYNC16(aD0 + st + 64, aP0 + akoff + 32);
        CP_ASYNC16(aD1 + st,      aP1 + akoff);
        CP_ASYNC16(aD1 + st + 64, aP1 + akoff + 32);
        CP_ASYNC16(bD0 + st,      bP0 + bk);
        CP_ASYNC16(bD0 + st + 64, bP0 + bk + 32);
        CP_ASYNC16(bD1 + st,      bP1 + bk);
        CP_ASYNC16(bD1 + st + 64, bP1 + bk + 32);
        CP_COMMIT();
    };

    issue(0);
    if (NC > 1) issue(1);

    const int gRow  = lane >> 2;
    const int cPair = (lane & 3) * 2;

    for (int c = 0; c < NC; c++) {
        if (c + 1 < NC) CP_WAIT1();
        else            CP_WAIT0();
        __syncthreads();
        if (c + 2 < NC) issue(c + 2);

        const uint32_t st = (uint32_t)(c % NSTG) * STG_STRIDE;
        const uint32_t aW = smBase + st + (warpM * 64) * 144;
        const uint32_t bW = smBase + st + B_STG_OFF + (warpN * 32) * 144;

        #pragma unroll
        for (int kh = 0; kh < 4; kh++) {
            uint32_t a[4][4], bf_[2][4];
            const uint32_t lrow = (lane & 15) * 144;
            const uint32_t lcol = kh * 32 + (lane >> 4) * 16;
            // B fragments + first A fragment
            LDMX4(bf_[0][0], bf_[0][1], bf_[0][2], bf_[0][3],
                  bW + lrow + lcol);
            LDMX4(bf_[1][0], bf_[1][1], bf_[1][2], bf_[1][3],
                  bW + 16 * 144 + lrow + lcol);
            LDMX4(a[0][0], a[0][1], a[0][2], a[0][3],
                  aW + lrow + lcol);
            // interleave: prefetch A[mt+1] before issuing mt's MMAs
            #pragma unroll
            for (int mt = 0; mt < 4; mt++) {
                if (mt < 3)
                    LDMX4(a[mt + 1][0], a[mt + 1][1], a[mt + 1][2], a[mt + 1][3],
                          aW + ((mt + 1) * 16) * 144 + lrow + lcol);
                MmaSel<T>::run(acc[mt][0], a[mt], bf_[0][0], bf_[0][2]);
                MmaSel<T>::run(acc[mt][1], a[mt], bf_[0][1], bf_[0][3]);
                MmaSel<T>::run(acc[mt][2], a[mt], bf_[1][0], bf_[1][2]);
                MmaSel<T>::run(acc[mt][3], a[mt], bf_[1][1], bf_[1][3]);
            }
        }
    }
    __syncthreads();

    // ---- epilogue ----
    #pragma unroll
    for (int mt = 0; mt < 4; mt++) {
        #pragma unroll
        for (int nt = 0; nt < 4; nt++) {
            const int n = n0 + warpN * 32 + nt * 8 + cPair;
            if (n >= Nreal) continue;
            const float b0 = bias[n], b1 = bias[n + 1];
            #pragma unroll
            for (int h = 0; h < 2; h++) {
                const long m = m0 + warpM * 64 + mt * 16 + h * 8 + gRow;
                if (STAGE == 5) {
                    float v0 = fmaf(-2.f, acc[mt][nt][h * 2 + 0], b0);
                    float v1 = fmaf(-2.f, acc[mt][nt][h * 2 + 1], b1);
                    *(__half2*)(outH + m * (long)outS + n) = __floats2half2_rn(v0, v1);
                    continue;
                }
                float v0 = acc[mt][nt][h * 2 + 0] + b0;
                float v1 = acc[mt][nt][h * 2 + 1] + b1;
                if (STAGE == 0 || STAGE == 6) { v0 = fmaxf(v0, 0.f); v1 = fmaxf(v1, 0.f); }
                if (STAGE == 4) {
                    float s0 = 1.f / (1.f + __expf(-v0));
                    float s1 = 1.f / (1.f + __expf(-v1));
                    *(float2*)(outF + m * (long)outS + n) = make_float2(s0, s1);
                } else if (STAGE == 6) {
                    *(__half2*)(outH + m * (long)outS + n) = __floats2half2_rn(v0, v1);
                } else {
                    bf16 t00 = __float2bfloat16(v0);
                    bf16 t01 = __float2bfloat16(v1);
                    float r0 = v0 - __bfloat162float(t00);
                    float r1 = v1 - __bfloat162float(t01);
                    bf16* d = outE + m * (long)outRow + n;
                    *(__nv_bfloat162*)(d)         = __nv_bfloat162(t00, t01);
                    *(__nv_bfloat162*)(d + outKP) =
                        __nv_bfloat162(__float2bfloat16(r0), __float2bfloat16(r1));
                }
            }
        }
    }
}

// ===========================================================================
// Launch (order: G1 is the 4th launch -> ncu capture slot)
// ===========================================================================
extern "C" void kernel_launch(void* const* d_in, const int* in_sizes, int n_in,
                              void* d_out, int out_size) {
    const float* x   = (const float*)d_in[0];
    const float* W1  = (const float*)d_in[1];
    const float* b1  = (const float*)d_in[2];
    const float* W2  = (const float*)d_in[3];
    const float* b2  = (const float*)d_in[4];
    const float* W3  = (const float*)d_in[5];
    const float* b3  = (const float*)d_in[6];
    const float* W4  = (const float*)d_in[7];
    const float* b4  = (const float*)d_in[8];
    const float* emb = (const float*)d_in[9];
    float* out = (float*)d_out;

    bf16 *xext, *h1e, *zee, *w1e, *w2e, *embq;
    __half *embh, *w3h, *h3h, *w4h, *Dh;
    float *en; int *idx;
    cudaGetSymbolAddress((void**)&xext, g_xext);
    cudaGetSymbolAddress((void**)&h1e,  g_h1e);
    cudaGetSymbolAddress((void**)&zee,  g_zee);
    cudaGetSymbolAddress((void**)&w1e,  g_w1e);
    cudaGetSymbolAddress((void**)&w2e,  g_w2e);
    cudaGetSymbolAddress((void**)&embq, g_embq);
    cudaGetSymbolAddress((void**)&embh, g_embh);
    cudaGetSymbolAddress((void**)&w3h,  g_w3h);
    cudaGetSymbolAddress((void**)&h3h,  g_h3h);
    cudaGetSymbolAddress((void**)&w4h,  g_w4h);
    cudaGetSymbolAddress((void**)&Dh,   g_Dh);
    cudaGetSymbolAddress((void**)&en,   g_en);
    cudaGetSymbolAddress((void**)&idx,  g_idx);

    const int SMEM = NSTG * STG_STRIDE;  // 110592
    cudaFuncSetAttribute(hgemm<0, false, bf16>,   cudaFuncAttributeMaxDynamicSharedMemorySize, SMEM);
    cudaFuncSetAttribute(hgemm<1, false, bf16>,   cudaFuncAttributeMaxDynamicSharedMemorySize, SMEM);
    cudaFuncSetAttribute(hgemm<5, false, bf16>,   cudaFuncAttributeMaxDynamicSharedMemorySize, SMEM);
    cudaFuncSetAttribute(hgemm<6, true,  __half>, cudaFuncAttributeMaxDynamicSharedMemorySize, SMEM);
    cudaFuncSetAttribute(hgemm<4, false, __half>, cudaFuncAttributeMaxDynamicSharedMemorySize, SMEM);

    // ---- launches 1..3: only G1's dependencies ----
    enorm_kernel<<<EMBED_NUM / 8, 256>>>(emb, en);                     // 1
    conv_A4<<<4096, 256>>>((const float4*)x, xext, (long)BZ, INPUT_DIM); // 2
    conv_B<<<2048, 256>>>(W1, w1e, HIDDEN, 512, INPUT_DIM, 1024);      // 3

    // ---- launch 4 (ncu slot): G1 = relu(x @ W1^T + b1) ----
    hgemm<0, false, bf16><<<dim3(128, 4), 256, SMEM>>>(                // 4
        xext, 2048, 1024, 16, 48, w1e, 3072, b1, HIDDEN, nullptr,
        h1e, 896, 448, nullptr, nullptr, 0);

    // ---- remaining prep ----
    conv_B<<<512,  256>>>(W2, w2e, EMBED_DIM, 256, HIDDEN, 448);
    f2bf<<<512, 256>>>(emb, embq, (long)EMBED_NUM * EMBED_DIM);
    f2h <<<512, 256>>>(emb, embh, (long)EMBED_NUM * EMBED_DIM);
    conv_Bh<<<256, 256>>>(W3, w3h, HIDDEN, 512, EMBED_DIM, 256);
    conv_Bh<<<512, 256>>>(W4, w4h, INPUT_DIM, 1024, HIDDEN, 448);
    zero_pad<<<512, 256>>>(h1e, BZ, HIDDEN, 448);
    zero_pad_h<<<512, 256>>>(h3h, BZ, HIDDEN, 448);

    // ---- G2: z_e = h1 @ W2^T + b2, bf16 3-product ----
    hgemm<1, false, bf16><<<dim3(128, 2), 256, SMEM>>>(
        h1e, 896, 448, 7, 21, w2e, 1344, b2, EMBED_DIM, nullptr,
        zee, 512, 256, nullptr, nullptr, 0);

    // ---- VQ prefilter: approx D (fp16 store), bf16 1-product ----
    hgemm<5, false, bf16><<<dim3(128, 16), 256, SMEM>>>(
        zee, 512, 256, 4, 4, embq, 256, en, EMBED_NUM, nullptr,
        nullptr, 0, 0, nullptr, Dh, EMBED_NUM);

    // ---- VQ exact refine ----
    scan_refine<<<BZ / 8, 256>>>(Dh, zee, emb, idx);

    // ---- G3: h3 = relu(emb[idx] @ W3^T + b3), fp16 1-product, gather ----
    hgemm<6, true, __half><<<dim3(128, 4), 256, SMEM>>>(
        embh, 256, 256, 4, 4, w3h, 256, b3, HIDDEN, idx,
        nullptr, 0, 0, nullptr, h3h, 448);

    // ---- G4: out = sigmoid(h3 @ W4^T + b4), fp16 1-product ----
    hgemm<4, false, __half><<<dim3(128, 8), 256, SMEM>>>(
        h3h, 448, 448, 7, 7, w4h, 448, b4, INPUT_DIM, nullptr,
        nullptr, 0, 0, out, nullptr, INPUT_DIM);
}